// round 1
// baseline (speedup 1.0000x reference)
#include <cuda_runtime.h>
#include <cuda_bf16.h>
#include <math_constants.h>

// Problem constants (fixed shapes from reference)
#define Bb 16
#define Cc 64
#define Hh 32
#define Ww 32
#define HW 1024           // H*W
#define Ntok 16384        // B*H*W
#define Kc 8192           // codebook size
#define DECAYF 0.99f
#define ONE_MINUS_DECAYF 0.01f
#define EPSF 1e-5f

// Output layout (float32, reference-return order, indices cast to float)
#define O_ZQST 0
#define O_IDX  1048576
#define O_ZQ   1064960
#define O_EMB  2113536
#define O_CS   2637824
#define O_AVG  2646016

// --------------------- scratch (device globals; no allocs allowed) ----------
__device__ float g_enorm[Kc];
__device__ int   g_idx[Ntok];
__device__ float g_counts[Kc];
__device__ float g_dw[Kc * Cc];
__device__ float g_n[1];

// --------------------- f32x2 helpers ---------------------------------------
typedef unsigned long long u64;

__device__ __forceinline__ u64 pack2(float x, float y) {
    u64 r;
    asm("mov.b64 %0, {%1, %2};" : "=l"(r) : "f"(x), "f"(y));
    return r;
}
__device__ __forceinline__ void fma2(u64 &d, u64 a, u64 b) {
    asm("fma.rn.f32x2 %0, %1, %2, %0;" : "+l"(d) : "l"(a), "l"(b));
}
__device__ __forceinline__ float2 unpack2(u64 v) {
    float2 r;
    asm("mov.b64 {%0, %1}, %2;" : "=f"(r.x), "=f"(r.y) : "l"(v));
    return r;
}

// --------------------- kernel 0: zero scratch -------------------------------
__global__ void zero_scratch_kernel() {
    int id = blockIdx.x * blockDim.x + threadIdx.x;
    if (id < Kc * Cc) g_dw[id] = 0.0f;
    if (id < Kc)      g_counts[id] = 0.0f;
}

// --------------------- kernel 1: ||e||^2 ------------------------------------
__global__ void enorm_kernel(const float* __restrict__ emb) {
    int k = blockIdx.x * blockDim.x + threadIdx.x;
    if (k >= Kc) return;
    const float4* p = reinterpret_cast<const float4*>(emb + (size_t)k * Cc);
    float s = 0.0f;
#pragma unroll
    for (int i = 0; i < Cc / 4; i++) {
        float4 v = p[i];
        s += v.x * v.x + v.y * v.y + v.z * v.z + v.w * v.w;
    }
    g_enorm[k] = s;
}

// --------------------- kernel 2: fused distance GEMM + argmin ----------------
// Block: 64 tokens. Loop over K in tiles of 64 codes. 256 threads = 16x16,
// each thread owns a 4(token) x 4(code) micro-tile, accumulators in f32x2.
#define BM 64
#define BN 64
#define SPAD 68   // row pad (floats), multiple of 4 for LDS.128 alignment

__global__ void __launch_bounds__(256) argmin_kernel(
    const float* __restrict__ z_e,
    const float* __restrict__ emb,
    int* __restrict__ out_idx)
{
    __shared__ float As[Cc * SPAD];   // [c][token], 64x68
    __shared__ float Bs[Cc * SPAD];   // [c][code],  64x68

    const int tid = threadIdx.x;
    const int n0  = blockIdx.x * BM;          // token base (aligned inside one b)
    const int b   = n0 >> 10;
    const int hw0 = n0 & (HW - 1);

    // Load A tile once: As[c][t] = z_e[b, c, hw0 + t]  (coalesced over t)
    const float* zb = z_e + (size_t)b * Cc * HW + hw0;
#pragma unroll
    for (int i = tid; i < BM * Cc; i += 256) {
        int c = i >> 6, t = i & 63;
        As[c * SPAD + t] = zb[c * HW + t];
    }

    const int ty = tid >> 4;   // token group: tokens ty*4 .. ty*4+3
    const int tx = tid & 15;   // code group:  codes  tx*4 .. tx*4+3 (per tile)

    float bestv[4];
    int   besti[4];
#pragma unroll
    for (int i = 0; i < 4; i++) { bestv[i] = CUDART_INF_F; besti[i] = 0; }

    for (int kt = 0; kt < Kc / BN; kt++) {
        __syncthreads();
        // Load B tile: Bs[c][code] = emb[kt*64 + code, c] (coalesced reads)
        const float* eb = emb + (size_t)kt * BN * Cc;
#pragma unroll
        for (int i = tid; i < BN * Cc; i += 256) {
            int code = i >> 6, c = i & 63;
            Bs[c * SPAD + code] = eb[code * Cc + c];
        }
        __syncthreads();

        // prefetch this thread's 4 code norms (L2-hot)
        float en0 = g_enorm[kt * BN + tx * 4 + 0];
        float en1 = g_enorm[kt * BN + tx * 4 + 1];
        float en2 = g_enorm[kt * BN + tx * 4 + 2];
        float en3 = g_enorm[kt * BN + tx * 4 + 3];

        u64 acc[4][2];
#pragma unroll
        for (int i = 0; i < 4; i++) { acc[i][0] = 0ull; acc[i][1] = 0ull; }

#pragma unroll 16
        for (int k = 0; k < Cc; k++) {
            float4 a4 = *reinterpret_cast<const float4*>(&As[k * SPAD + ty * 4]);
            float4 b4 = *reinterpret_cast<const float4*>(&Bs[k * SPAD + tx * 4]);
            u64 b01 = pack2(b4.x, b4.y);
            u64 b23 = pack2(b4.z, b4.w);
            u64 aa;
            aa = pack2(a4.x, a4.x); fma2(acc[0][0], aa, b01); fma2(acc[0][1], aa, b23);
            aa = pack2(a4.y, a4.y); fma2(acc[1][0], aa, b01); fma2(acc[1][1], aa, b23);
            aa = pack2(a4.z, a4.z); fma2(acc[2][0], aa, b01); fma2(acc[2][1], aa, b23);
            aa = pack2(a4.w, a4.w); fma2(acc[3][0], aa, b01); fma2(acc[3][1], aa, b23);
        }

        // fold tile into running argmin (dist = ||e||^2 - 2*dot; scan j ascending)
        int cbase = kt * BN + tx * 4;
#pragma unroll
        for (int i = 0; i < 4; i++) {
            float2 d01 = unpack2(acc[i][0]);
            float2 d23 = unpack2(acc[i][1]);
            float d;
            d = fmaf(-2.0f, d01.x, en0); if (d < bestv[i]) { bestv[i] = d; besti[i] = cbase + 0; }
            d = fmaf(-2.0f, d01.y, en1); if (d < bestv[i]) { bestv[i] = d; besti[i] = cbase + 1; }
            d = fmaf(-2.0f, d23.x, en2); if (d < bestv[i]) { bestv[i] = d; besti[i] = cbase + 2; }
            d = fmaf(-2.0f, d23.y, en3); if (d < bestv[i]) { bestv[i] = d; besti[i] = cbase + 3; }
        }
    }

    // Reduce across the 16 tx-lanes sharing each token (lower index wins ties)
#pragma unroll
    for (int i = 0; i < 4; i++) {
        float v = bestv[i];
        int   ix = besti[i];
#pragma unroll
        for (int off = 8; off >= 1; off >>= 1) {
            float ov = __shfl_xor_sync(0xffffffffu, v, off, 16);
            int   oi = __shfl_xor_sync(0xffffffffu, ix, off, 16);
            if (ov < v || (ov == v && oi < ix)) { v = ov; ix = oi; }
        }
        if (tx == 0) out_idx[n0 + ty * 4 + i] = ix;
    }
}

// --------------------- kernel 3: EMA scatter (counts, dw) --------------------
__global__ void ema_scatter_kernel(const float* __restrict__ z_e) {
    int id = blockIdx.x * blockDim.x + threadIdx.x;   // over Ntok * Cc, n fastest
    if (id >= Ntok * Cc) return;
    int n = id & (Ntok - 1);
    int c = id >> 14;
    int b = n >> 10, hw = n & (HW - 1);
    float v = z_e[(size_t)b * Cc * HW + c * HW + hw];
    int e = g_idx[n];
    atomicAdd(&g_dw[e * Cc + c], v);
    if (c == 0) atomicAdd(&g_counts[e], 1.0f);
}

// --------------------- kernel 4: gather outputs (z_q_st, z_q, indices) -------
__global__ void outputs_kernel(const float* __restrict__ z_e,
                               const float* __restrict__ emb,
                               float* __restrict__ out)
{
    int id = blockIdx.x * blockDim.x + threadIdx.x;   // over B*C*H*W
    if (id >= Bb * Cc * HW) return;
    int hw = id & (HW - 1);
    int c  = (id >> 10) & (Cc - 1);
    int b  = id >> 16;
    int n  = b * HW + hw;
    int e  = g_idx[n];
    float zq = emb[e * Cc + c];
    float ze = z_e[id];
    out[O_ZQST + id] = ze + (zq - ze);   // straight-through value == z_q
    out[O_ZQ   + id] = zq;
    if (id < Ntok) out[O_IDX + id] = (float)g_idx[id];
}

// --------------------- kernel 5: EMA blend -----------------------------------
__global__ void finalize1_kernel(const float* __restrict__ cs_in,
                                 const float* __restrict__ avg_in,
                                 float* __restrict__ out)
{
    int id = blockIdx.x * blockDim.x + threadIdx.x;   // over K*C
    if (id >= Kc * Cc) return;
    out[O_AVG + id] = DECAYF * avg_in[id] + ONE_MINUS_DECAYF * g_dw[id];
    if (id < Kc)
        out[O_CS + id] = DECAYF * cs_in[id] + ONE_MINUS_DECAYF * g_counts[id];
}

// --------------------- kernel 6: n = sum(new_cluster_size) -------------------
__global__ void reduce_n_kernel(const float* __restrict__ out) {
    __shared__ float s[1024];
    int tid = threadIdx.x;
    float acc = 0.0f;
    for (int i = tid; i < Kc; i += 1024) acc += out[O_CS + i];
    s[tid] = acc;
    __syncthreads();
    for (int off = 512; off > 0; off >>= 1) {
        if (tid < off) s[tid] += s[tid + off];
        __syncthreads();
    }
    if (tid == 0) g_n[0] = s[0];
}

// --------------------- kernel 7: normalized embedding ------------------------
__global__ void finalize2_kernel(float* __restrict__ out) {
    int id = blockIdx.x * blockDim.x + threadIdx.x;   // over K*C
    if (id >= Kc * Cc) return;
    int k = id >> 6;
    float n = g_n[0];
    float cs = (out[O_CS + k] + EPSF) / (n + (float)Kc * EPSF) * n;
    out[O_EMB + id] = out[O_AVG + id] / cs;
}

// --------------------- launcher ---------------------------------------------
extern "C" void kernel_launch(void* const* d_in, const int* in_sizes, int n_in,
                              void* d_out, int out_size)
{
    const float* z_e  = (const float*)d_in[0];
    const float* emb  = (const float*)d_in[1];
    const float* cs   = (const float*)d_in[2];
    const float* avg  = (const float*)d_in[3];
    float* out = (float*)d_out;

    int* idx_ptr = nullptr;
    cudaGetSymbolAddress((void**)&idx_ptr, g_idx);   // host API, not capture-relevant?
    // NOTE: cudaGetSymbolAddress is a pure address query (no alloc, no stream op);
    // but to stay strictly capture-safe we avoid it: kernels reference g_idx directly.
    (void)idx_ptr;

    zero_scratch_kernel<<<(Kc * Cc + 255) / 256, 256>>>();
    enorm_kernel<<<(Kc + 255) / 256, 256>>>(emb);

    int* d_idx;
    cudaGetSymbolAddress((void**)&d_idx, g_idx);
    argmin_kernel<<<Ntok / BM, 256>>>(z_e, emb, d_idx);

    ema_scatter_kernel<<<(Ntok * Cc + 255) / 256, 256>>>(z_e);
    outputs_kernel<<<(Bb * Cc * HW + 255) / 256, 256>>>(z_e, emb, out);
    finalize1_kernel<<<(Kc * Cc + 255) / 256, 256>>>(cs, avg, out);
    reduce_n_kernel<<<1, 1024>>>(out);
    finalize2_kernel<<<(Kc * Cc + 255) / 256, 256>>>(out);
}

// round 4
// speedup vs baseline: 1.2699x; 1.2699x over previous
#include <cuda_runtime.h>
#include <cuda_bf16.h>
#include <math_constants.h>

// Problem constants (fixed shapes from reference)
#define Bb 16
#define Cc 64
#define HW 1024           // H*W
#define Ntok 16384        // B*H*W
#define Kc 8192           // codebook size
#define DECAYF 0.99f
#define ONE_MINUS_DECAYF 0.01f
#define EPSF 1e-5f

// Output layout (float32, reference-return order, indices cast to float)
#define O_ZQST 0
#define O_IDX  1048576
#define O_ZQ   1064960
#define O_EMB  2113536
#define O_CS   2637824
#define O_AVG  2646016

// --------------------- scratch (device globals; no allocs allowed) ----------
__device__ float              g_enorm[Kc];
__device__ unsigned long long g_key[Ntok];     // (ordered_float(d)<<32) | code_idx
__device__ float              g_counts[Kc];
__device__ float              g_dw[Kc * Cc];
__device__ float              g_n[1];

typedef unsigned long long u64;
typedef unsigned int       u32;

// --------------------- f32x2 helpers ---------------------------------------
__device__ __forceinline__ u64 pack2(float x, float y) {
    u64 r;
    asm("mov.b64 %0, {%1, %2};" : "=l"(r) : "f"(x), "f"(y));
    return r;
}
__device__ __forceinline__ void fma2(u64 &d, u64 a, u64 b) {
    asm("fma.rn.f32x2 %0, %1, %2, %0;" : "+l"(d) : "l"(a), "l"(b));
}
__device__ __forceinline__ float2 unpack2(u64 v) {
    float2 r;
    asm("mov.b64 {%0, %1}, %2;" : "=f"(r.x), "=f"(r.y) : "l"(v));
    return r;
}
// monotone unsigned encoding of float (preserves < ordering for all finite)
__device__ __forceinline__ u32 fmono(float f) {
    u32 u = __float_as_uint(f);
    return u ^ ((u32)(((int)u) >> 31) | 0x80000000u);
}

// --------------------- kernel 0a: zero dw ------------------------------------
__global__ void zero_dw_kernel() {
    int id = blockIdx.x * blockDim.x + threadIdx.x;
    if (id < Kc * Cc / 4) reinterpret_cast<float4*>(g_dw)[id] = make_float4(0,0,0,0);
}

// --------------------- kernel 0b: zero counts/key/n --------------------------
__global__ void zero_misc_kernel() {
    int id = blockIdx.x * blockDim.x + threadIdx.x;
    if (id < Kc) g_counts[id] = 0.0f;
    if (id < Ntok) g_key[id] = 0xFFFFFFFFFFFFFFFFull;
    if (id == 0) g_n[0] = 0.0f;
}

// --------------------- kernel 1: ||e||^2 ------------------------------------
__global__ void enorm_kernel(const float* __restrict__ emb) {
    int k = blockIdx.x * blockDim.x + threadIdx.x;
    if (k >= Kc) return;
    const float4* p = reinterpret_cast<const float4*>(emb + (size_t)k * Cc);
    float s = 0.0f;
#pragma unroll
    for (int i = 0; i < Cc / 4; i++) {
        float4 v = p[i];
        s += v.x * v.x + v.y * v.y + v.z * v.z + v.w * v.w;
    }
    g_enorm[k] = s;
}

// --------------------- kernel 2: fused distance GEMM + argmin ----------------
// Grid: 2048 blocks = 16 code-chunks (outer) x 128 token-tiles (inner).
// Block: 256 threads, token-tile BM=128, per code-chunk 8 tiles of BN=64.
// Per-thread micro-tile: 8 tokens x 4 codes; accumulators are f32x2 (token pair).
#define BM 128
#define BN 64
#define BPAD 68
#define TILES_PER_CHUNK 8
#define CHUNKS 16
#define SMEM_A_FLOATS (Cc * BM)            // 8192
#define SMEM_B_FLOATS (Cc * BPAD)          // 4352
#define ARGMIN_SMEM ((SMEM_A_FLOATS + SMEM_B_FLOATS) * 4)

__device__ __forceinline__ int bswz(int r) { return ((r >> 3) & 3) << 2; }

__global__ void __launch_bounds__(256, 2) argmin_kernel(
    const float* __restrict__ z_e,
    const float* __restrict__ emb)
{
    extern __shared__ float smem[];
    float* As = smem;                    // [c][token] 64 x 128
    float* Bs = smem + SMEM_A_FLOATS;    // [c][code^swz] 64 x 68

    const int tid   = threadIdx.x;
    const int tt    = blockIdx.x & 127;        // token tile
    const int chunk = blockIdx.x >> 7;         // code chunk
    const int n0    = tt * BM;
    const int b     = n0 >> 10;
    const int hw0   = n0 & (HW - 1);

    // Load A tile once: As[c][t] = z_e[b, c, hw0 + t]  (coalesced, conflict-free)
    const float* zb = z_e + (size_t)b * Cc * HW + hw0;
    for (int i = tid; i < BM * Cc; i += 256) {
        int c = i >> 7, t = i & 127;
        As[c * BM + t] = zb[c * HW + t];
    }

    const int ty = tid >> 4;   // token group: tokens ty*8 .. ty*8+7
    const int tx = tid & 15;   // code group:  codes  tx*4 .. tx*4+3 per tile

    float bestv[8];
    int   besti[8];
#pragma unroll
    for (int i = 0; i < 8; i++) { bestv[i] = CUDART_INF_F; besti[i] = 0; }

    for (int tile = 0; tile < TILES_PER_CHUNK; tile++) {
        const int code0 = chunk * (BN * TILES_PER_CHUNK) + tile * BN;
        __syncthreads();
        // Load B tile (swizzled): Bs[c][code ^ swz(c)] = emb[code0+code, c]
        const float* eb = emb + (size_t)code0 * Cc;
        for (int i = tid; i < BN * Cc; i += 256) {
            int code = i >> 6, c = i & 63;
            Bs[c * BPAD + (code ^ bswz(c))] = eb[code * Cc + c];
        }
        __syncthreads();

        float en[4];
#pragma unroll
        for (int j = 0; j < 4; j++) en[j] = g_enorm[code0 + tx * 4 + j];

        u64 acc[4][4];   // [token pair][code]
#pragma unroll
        for (int p = 0; p < 4; p++)
#pragma unroll
            for (int j = 0; j < 4; j++) acc[p][j] = 0ull;

        const int bcol = tx * 4;
#pragma unroll 16
        for (int k = 0; k < Cc; k++) {
            ulonglong2 a01 = *reinterpret_cast<const ulonglong2*>(&As[k * BM + ty * 8]);
            ulonglong2 a23 = *reinterpret_cast<const ulonglong2*>(&As[k * BM + ty * 8 + 4]);
            float4 b4 = *reinterpret_cast<const float4*>(&Bs[k * BPAD + (bcol ^ bswz(k))]);
            u64 s0 = pack2(b4.x, b4.x);
            u64 s1 = pack2(b4.y, b4.y);
            u64 s2 = pack2(b4.z, b4.z);
            u64 s3 = pack2(b4.w, b4.w);
            fma2(acc[0][0], a01.x, s0); fma2(acc[0][1], a01.x, s1);
            fma2(acc[0][2], a01.x, s2); fma2(acc[0][3], a01.x, s3);
            fma2(acc[1][0], a01.y, s0); fma2(acc[1][1], a01.y, s1);
            fma2(acc[1][2], a01.y, s2); fma2(acc[1][3], a01.y, s3);
            fma2(acc[2][0], a23.x, s0); fma2(acc[2][1], a23.x, s1);
            fma2(acc[2][2], a23.x, s2); fma2(acc[2][3], a23.x, s3);
            fma2(acc[3][0], a23.y, s0); fma2(acc[3][1], a23.y, s1);
            fma2(acc[3][2], a23.y, s2); fma2(acc[3][3], a23.y, s3);
        }

        // fold tile into running argmin: d = ||e||^2 - 2*dot (ascending code idx)
#pragma unroll
        for (int p = 0; p < 4; p++) {
#pragma unroll
            for (int j = 0; j < 4; j++) {
                float2 dd = unpack2(acc[p][j]);
                int cidx = code0 + bcol + j;
                float dlo = fmaf(-2.0f, dd.x, en[j]);
                float dhi = fmaf(-2.0f, dd.y, en[j]);
                int t0 = 2 * p, t1 = 2 * p + 1;
                if (dlo < bestv[t0]) { bestv[t0] = dlo; besti[t0] = cidx; }
                if (dhi < bestv[t1]) { bestv[t1] = dhi; besti[t1] = cidx; }
            }
        }
    }

    // Reduce across the 16 tx-lanes sharing each token (lower index wins ties),
    // then merge across chunks via atomic min on a monotone key.
#pragma unroll
    for (int i = 0; i < 8; i++) {
        float v = bestv[i];
        int   ix = besti[i];
#pragma unroll
        for (int off = 8; off >= 1; off >>= 1) {
            float ov = __shfl_xor_sync(0xffffffffu, v, off, 16);
            int   oi = __shfl_xor_sync(0xffffffffu, ix, off, 16);
            if (ov < v || (ov == v && oi < ix)) { v = ov; ix = oi; }
        }
        if (tx == 0) {
            u64 key = ((u64)fmono(v) << 32) | (u32)ix;
            asm volatile("red.global.min.u64 [%0], %1;"
                         :: "l"(&g_key[n0 + ty * 8 + i]), "l"(key) : "memory");
        }
    }
}

// --------------------- kernel 3: EMA scatter (counts, dw) --------------------
__global__ void ema_scatter_kernel(const float* __restrict__ z_e) {
    int id = blockIdx.x * blockDim.x + threadIdx.x;   // over Ntok * Cc, n fastest
    if (id >= Ntok * Cc) return;
    int n = id & (Ntok - 1);
    int c = id >> 14;
    int b = n >> 10, hw = n & (HW - 1);
    float v = z_e[(size_t)b * Cc * HW + c * HW + hw];
    int e = (int)(g_key[n] & 0xFFFFFFFFull);
    atomicAdd(&g_dw[e * Cc + c], v);
    if (c == 0) atomicAdd(&g_counts[e], 1.0f);
}

// --------------------- kernel 4: gather outputs (z_q_st, z_q, indices) -------
__global__ void outputs_kernel(const float* __restrict__ z_e,
                               const float* __restrict__ emb,
                               float* __restrict__ out)
{
    int id = blockIdx.x * blockDim.x + threadIdx.x;   // over B*C*H*W / 4
    if (id >= Bb * Cc * HW / 4) return;
    int hwq = id & 255;              // hw quad
    int c   = (id >> 8) & 63;
    int b   = id >> 14;
    int nb  = b * HW + hwq * 4;

    float4 ze = reinterpret_cast<const float4*>(z_e)[id];
    int e0 = (int)(g_key[nb + 0] & 0xFFFFFFFFull);
    int e1 = (int)(g_key[nb + 1] & 0xFFFFFFFFull);
    int e2 = (int)(g_key[nb + 2] & 0xFFFFFFFFull);
    int e3 = (int)(g_key[nb + 3] & 0xFFFFFFFFull);
    float4 zq;
    zq.x = emb[e0 * Cc + c];
    zq.y = emb[e1 * Cc + c];
    zq.z = emb[e2 * Cc + c];
    zq.w = emb[e3 * Cc + c];
    float4 st;
    st.x = ze.x + (zq.x - ze.x);
    st.y = ze.y + (zq.y - ze.y);
    st.z = ze.z + (zq.z - ze.z);
    st.w = ze.w + (zq.w - ze.w);
    reinterpret_cast<float4*>(out + O_ZQST)[id] = st;
    reinterpret_cast<float4*>(out + O_ZQ)[id]   = zq;

    if (id < Ntok / 4) {
        int n = id * 4;
        float4 ix;
        ix.x = (float)(int)(g_key[n + 0] & 0xFFFFFFFFull);
        ix.y = (float)(int)(g_key[n + 1] & 0xFFFFFFFFull);
        ix.z = (float)(int)(g_key[n + 2] & 0xFFFFFFFFull);
        ix.w = (float)(int)(g_key[n + 3] & 0xFFFFFFFFull);
        reinterpret_cast<float4*>(out + O_IDX)[id] = ix;
    }
}

// --------------------- kernel 5: EMA blend + n reduction ---------------------
__global__ void finalize1_kernel(const float* __restrict__ cs_in,
                                 const float* __restrict__ avg_in,
                                 float* __restrict__ out)
{
    int id = blockIdx.x * blockDim.x + threadIdx.x;   // over K*C/4
    if (id >= Kc * Cc / 4) return;
    float4 av = reinterpret_cast<const float4*>(avg_in)[id];
    float4 dw = reinterpret_cast<const float4*>(g_dw)[id];
    float4 r;
    r.x = DECAYF * av.x + ONE_MINUS_DECAYF * dw.x;
    r.y = DECAYF * av.y + ONE_MINUS_DECAYF * dw.y;
    r.z = DECAYF * av.z + ONE_MINUS_DECAYF * dw.z;
    r.w = DECAYF * av.w + ONE_MINUS_DECAYF * dw.w;
    reinterpret_cast<float4*>(out + O_AVG)[id] = r;

    if (id < Kc / 4) {
        float4 cv = reinterpret_cast<const float4*>(cs_in)[id];
        float4 ct = reinterpret_cast<const float4*>(g_counts)[id];
        float4 cs;
        cs.x = DECAYF * cv.x + ONE_MINUS_DECAYF * ct.x;
        cs.y = DECAYF * cv.y + ONE_MINUS_DECAYF * ct.y;
        cs.z = DECAYF * cv.z + ONE_MINUS_DECAYF * ct.z;
        cs.w = DECAYF * cv.w + ONE_MINUS_DECAYF * ct.w;
        reinterpret_cast<float4*>(out + O_CS)[id] = cs;
        float local = cs.x + cs.y + cs.z + cs.w;
#pragma unroll
        for (int off = 16; off >= 1; off >>= 1)
            local += __shfl_xor_sync(0xffffffffu, local, off);
        if ((threadIdx.x & 31) == 0) atomicAdd(g_n, local);
    }
}

// --------------------- kernel 6: normalized embedding ------------------------
__global__ void finalize2_kernel(float* __restrict__ out) {
    int id = blockIdx.x * blockDim.x + threadIdx.x;   // over K*C/4
    if (id >= Kc * Cc / 4) return;
    int k = id >> 4;                                  // 16 quads per code row
    float n = g_n[0];
    float csv = out[O_CS + k];
    float cs = (csv + EPSF) / (n + (float)Kc * EPSF) * n;
    float inv = 1.0f / cs;
    float4 av = reinterpret_cast<const float4*>(out + O_AVG)[id];
    float4 r;
    r.x = av.x * inv; r.y = av.y * inv; r.z = av.z * inv; r.w = av.w * inv;
    reinterpret_cast<float4*>(out + O_EMB)[id] = r;
}

// --------------------- launcher ---------------------------------------------
extern "C" void kernel_launch(void* const* d_in, const int* in_sizes, int n_in,
                              void* d_out, int out_size)
{
    const float* z_e  = (const float*)d_in[0];
    const float* emb  = (const float*)d_in[1];
    const float* cs   = (const float*)d_in[2];
    const float* avg  = (const float*)d_in[3];
    float* out = (float*)d_out;

    cudaFuncSetAttribute(argmin_kernel,
                         cudaFuncAttributeMaxDynamicSharedMemorySize, ARGMIN_SMEM);

    zero_dw_kernel<<<(Kc * Cc / 4 + 255) / 256, 256>>>();
    zero_misc_kernel<<<(Ntok + 255) / 256, 256>>>();
    enorm_kernel<<<(Kc + 255) / 256, 256>>>(emb);
    argmin_kernel<<<128 * CHUNKS, 256, ARGMIN_SMEM>>>(z_e, emb);
    ema_scatter_kernel<<<(Ntok * Cc + 255) / 256, 256>>>(z_e);
    outputs_kernel<<<(Bb * Cc * HW / 4 + 255) / 256, 256>>>(z_e, emb, out);
    finalize1_kernel<<<(Kc * Cc / 4 + 255) / 256, 256>>>(cs, avg, out);
    finalize2_kernel<<<(Kc * Cc / 4 + 255) / 256, 256>>>(out);
}

// round 6
// speedup vs baseline: 1.4912x; 1.1743x over previous
#include <cuda_runtime.h>
#include <cuda_bf16.h>
#include <math_constants.h>
#include <cstdint>

typedef unsigned long long u64;
typedef unsigned int       u32;
typedef unsigned short     u16;

// Problem constants
#define Bb 16
#define Cc 64
#define HW 1024
#define Ntok 16384
#define Kc 8192
#define DECAYF 0.99f
#define ONE_MINUS_DECAYF 0.01f
#define EPSF 1e-5f

// Output layout (float32, reference-return order)
#define O_ZQST 0
#define O_IDX  1048576
#define O_ZQ   1064960
#define O_EMB  2113536
#define O_CS   2637824
#define O_AVG  2646016

// K-concat split GEMM: K_total = 6 segments x 64 = 384
#define NSEG 6
#define KTOT 384
#define ROW_U32 192           // 384 bf16 = 192 u32 per row

// --------------------- scratch (device globals) ------------------------------
__device__ u32   g_Ap[Ntok * ROW_U32];   // A' token-major [16384][384] bf16
__device__ u32   g_Bp[Kc * ROW_U32];     // B' code-major  [8192][384] bf16
__device__ float g_enorm[Kc];
__device__ u64   g_key[Ntok];            // (fmono(dist)<<32) | code
__device__ float g_counts[Kc];
__device__ float g_dw[Kc * Cc];
__device__ float g_n[1];

// --------------------- helpers ----------------------------------------------
__device__ __forceinline__ u32 fmono(float f) {
    u32 u = __float_as_uint(f);
    return u ^ ((u32)(((int)u) >> 31) | 0x80000000u);
}
__device__ __forceinline__ u32 smem_u32(const void* p) {
    u32 a;
    asm("{ .reg .u64 t; cvta.to.shared.u64 t, %1; cvt.u32.u64 %0, t; }" : "=r"(a) : "l"(p));
    return a;
}
#define CP_ASYNC16(dst, src) \
    asm volatile("cp.async.cg.shared.global [%0], [%1], 16;" :: "r"(dst), "l"(src))
#define CP_COMMIT() asm volatile("cp.async.commit_group;" ::: "memory")
#define CP_WAIT(n)  asm volatile("cp.async.wait_group %0;" :: "n"(n) : "memory")

__device__ __forceinline__ void mma16816(float* d, const u32* a, const u32* b) {
    asm volatile("mma.sync.aligned.m16n8k16.row.col.f32.bf16.bf16.f32 "
        "{%0,%1,%2,%3}, {%4,%5,%6,%7}, {%8,%9}, {%0,%1,%2,%3};"
        : "+f"(d[0]), "+f"(d[1]), "+f"(d[2]), "+f"(d[3])
        : "r"(a[0]), "r"(a[1]), "r"(a[2]), "r"(a[3]), "r"(b[0]), "r"(b[1]));
}

// --------------------- bf16 3-way split --------------------------------------
__device__ __forceinline__ void split3(float a, u16 &h1, u16 &h2, u16 &h3) {
    __nv_bfloat16 b1 = __float2bfloat16(a);
    float r = a - __bfloat162float(b1);
    __nv_bfloat16 b2 = __float2bfloat16(r);
    float r2 = r - __bfloat162float(b2);
    __nv_bfloat16 b3 = __float2bfloat16(r2);
    h1 = __bfloat16_as_ushort(b1);
    h2 = __bfloat16_as_ushort(b2);
    h3 = __bfloat16_as_ushort(b3);
}

// --------------------- zero / init kernels -----------------------------------
__global__ void zero_dw_kernel() {
    int id = blockIdx.x * blockDim.x + threadIdx.x;
    if (id < Kc * Cc / 4) reinterpret_cast<float4*>(g_dw)[id] = make_float4(0, 0, 0, 0);
}
__global__ void zero_misc_kernel() {
    int id = blockIdx.x * blockDim.x + threadIdx.x;
    if (id < Kc) g_counts[id] = 0.0f;
    if (id < Ntok) g_key[id] = 0xFFFFFFFFFFFFFFFFull;
    if (id == 0) g_n[0] = 0.0f;
}

// --------------------- ||e||^2 ------------------------------------------------
__global__ void enorm_kernel(const float* __restrict__ emb) {
    int k = blockIdx.x * blockDim.x + threadIdx.x;
    if (k >= Kc) return;
    const float4* p = reinterpret_cast<const float4*>(emb + (size_t)k * Cc);
    float s = 0.0f;
#pragma unroll
    for (int i = 0; i < Cc / 4; i++) {
        float4 v = p[i];
        s += v.x * v.x + v.y * v.y + v.z * v.z + v.w * v.w;
    }
    g_enorm[k] = s;
}

// --------------------- split z: A' = [a1,a1,a2,a2,a1,a3] of (-2z), token-major
__global__ void __launch_bounds__(256) zsplit_kernel(const float* __restrict__ z_e) {
    __shared__ float st[Cc * 65];
    const int tid = threadIdx.x;
    const int n0 = blockIdx.x * 64;
    const int b = n0 >> 10, hw0 = n0 & (HW - 1);
    const float* zb = z_e + (size_t)b * Cc * HW + hw0;
    for (int i = tid; i < 64 * Cc; i += 256) {
        int c = i >> 6, t = i & 63;
        st[c * 65 + t] = zb[c * HW + t];
    }
    __syncthreads();
    const int cp = tid & 31;           // channel pair 0..31
#pragma unroll
    for (int it = 0; it < 8; it++) {
        int t = (tid >> 5) + it * 8;
        float x0 = -2.0f * st[(2 * cp) * 65 + t];
        float x1 = -2.0f * st[(2 * cp + 1) * 65 + t];
        u16 a1, a2, a3, b1, b2, b3;
        split3(x0, a1, a2, a3);
        split3(x1, b1, b2, b3);
        u32 p1 = (u32)a1 | ((u32)b1 << 16);
        u32 p2 = (u32)a2 | ((u32)b2 << 16);
        u32 p3 = (u32)a3 | ((u32)b3 << 16);
        int o = (n0 + t) * ROW_U32 + cp;
        g_Ap[o +   0] = p1;
        g_Ap[o +  32] = p1;
        g_Ap[o +  64] = p2;
        g_Ap[o +  96] = p2;
        g_Ap[o + 128] = p1;
        g_Ap[o + 160] = p3;
    }
}

// --------------------- split e: B' = [b1,b2,b1,b2,b3,b1], code-major ----------
__global__ void __launch_bounds__(256) esplit_kernel(const float* __restrict__ emb) {
    int id = blockIdx.x * blockDim.x + threadIdx.x;   // over Kc*32
    if (id >= Kc * 32) return;
    int code = id >> 5, cp = id & 31;
    float2 e2 = reinterpret_cast<const float2*>(emb)[id];
    u16 a1, a2, a3, b1, b2, b3;
    split3(e2.x, a1, a2, a3);
    split3(e2.y, b1, b2, b3);
    u32 p1 = (u32)a1 | ((u32)b1 << 16);
    u32 p2 = (u32)a2 | ((u32)b2 << 16);
    u32 p3 = (u32)a3 | ((u32)b3 << 16);
    int o = code * ROW_U32 + cp;
    g_Bp[o +   0] = p1;
    g_Bp[o +  32] = p2;
    g_Bp[o +  64] = p1;
    g_Bp[o +  96] = p2;
    g_Bp[o + 128] = p3;
    g_Bp[o + 160] = p1;
}

// --------------------- argmin: mma.sync bf16 GEMM + fused argmin -------------
// Grid 8192 = 128 token-tiles x 64 code-tiles. CTA tile 128x128, K=384 in 6
// stages of 64. 8 warps as 4(m) x 2(n); warp tile 32x64 via m16n8k16.
#define ROWB 144                 // smem row stride bytes (64 bf16 + 8 pad)
#define A_STAGE 18432            // 128 * 144
#define SM_A 0                   // + s*A_STAGE
#define SM_B 36864               // + s*A_STAGE
#define SM_EN 73728
#define SM_KEYS 74240
#define ARG_SMEM 75264

__global__ void __launch_bounds__(256, 2) argmin_kernel() {
    extern __shared__ char smem[];
    const int tid = threadIdx.x;
    const int lane = tid & 31;
    const int wid = tid >> 5;
    const int warp_m = wid >> 1, warp_n = wid & 1;
    const int gID = lane >> 2, tg = lane & 3;
    const int tt = blockIdx.x >> 6;       // token tile
    const int ct = blockIdx.x & 63;       // code tile
    const u32 sb = smem_u32(smem);

    if (tid < 128) {
        reinterpret_cast<u64*>(smem + SM_KEYS)[tid] = 0xFFFFFFFFFFFFFFFFull;
        reinterpret_cast<float*>(smem + SM_EN)[tid] = g_enorm[ct * 128 + tid];
    }

    // stage loader: 128 rows x 128 bytes for A and B
    auto load_stage = [&](int kt, int s) {
        const char* gA = reinterpret_cast<const char*>(g_Ap)
                       + ((size_t)tt * 128) * 768 + kt * 128;
        const char* gB = reinterpret_cast<const char*>(g_Bp)
                       + ((size_t)ct * 128) * 768 + kt * 128;
        for (int j = tid; j < 1024; j += 256) {
            int r = j >> 3, c = j & 7;
            CP_ASYNC16(sb + SM_A + s * A_STAGE + r * ROWB + c * 16, gA + (size_t)r * 768 + c * 16);
        }
        for (int j = tid; j < 1024; j += 256) {
            int r = j >> 3, c = j & 7;
            CP_ASYNC16(sb + SM_B + s * A_STAGE + r * ROWB + c * 16, gB + (size_t)r * 768 + c * 16);
        }
    };

    load_stage(0, 0);
    CP_COMMIT();

    float d[2][8][4];
#pragma unroll
    for (int mt = 0; mt < 2; mt++)
#pragma unroll
        for (int nt = 0; nt < 8; nt++)
#pragma unroll
            for (int i = 0; i < 4; i++) d[mt][nt][i] = 0.0f;

    for (int kt = 0; kt < NSEG; kt++) {
        if (kt + 1 < NSEG) { load_stage(kt + 1, (kt + 1) & 1); CP_COMMIT(); CP_WAIT(1); }
        else               { CP_WAIT(0); }
        __syncthreads();

        const char* aB = smem + SM_A + (kt & 1) * A_STAGE
                       + (warp_m * 32 + gID) * ROWB + tg * 4;
        const char* bB = smem + SM_B + (kt & 1) * A_STAGE
                       + (warp_n * 64 + gID) * ROWB + tg * 4;
#pragma unroll
        for (int ks = 0; ks < 4; ks++) {
            u32 a[2][4];
#pragma unroll
            for (int mt = 0; mt < 2; mt++) {
                const char* p = aB + mt * (16 * ROWB) + ks * 32;
                a[mt][0] = *reinterpret_cast<const u32*>(p);
                a[mt][1] = *reinterpret_cast<const u32*>(p + 8 * ROWB);
                a[mt][2] = *reinterpret_cast<const u32*>(p + 16);
                a[mt][3] = *reinterpret_cast<const u32*>(p + 8 * ROWB + 16);
            }
#pragma unroll
            for (int nt = 0; nt < 8; nt++) {
                u32 b[2];
                const char* p = bB + nt * (8 * ROWB) + ks * 32;
                b[0] = *reinterpret_cast<const u32*>(p);
                b[1] = *reinterpret_cast<const u32*>(p + 16);
                mma16816(d[0][nt], a[0], b);
                mma16816(d[1][nt], a[1], b);
            }
        }
        __syncthreads();
    }

    // epilogue: dist = ||e||^2 - 2 z.e ; fold per-thread argmin per row
    const int code0 = ct * 128 + warp_n * 64;
    const float* en = reinterpret_cast<const float*>(smem + SM_EN) + warp_n * 64;
    u64* keys = reinterpret_cast<u64*>(smem + SM_KEYS);
#pragma unroll
    for (int mt = 0; mt < 2; mt++) {
#pragma unroll
        for (int h = 0; h < 2; h++) {
            int row = warp_m * 32 + mt * 16 + gID + h * 8;
            float bv = CUDART_INF_F;
            int bi = 0;
#pragma unroll
            for (int nt = 0; nt < 8; nt++) {
#pragma unroll
                for (int c = 0; c < 2; c++) {
                    int l = nt * 8 + tg * 2 + c;
                    float v = d[mt][nt][h * 2 + c] + en[l];
                    if (v < bv) { bv = v; bi = code0 + l; }
                }
            }
            u64 key = ((u64)fmono(bv) << 32) | (u32)bi;
            atomicMin(&keys[row], key);
        }
    }
    __syncthreads();
    if (tid < 128) {
        asm volatile("red.global.min.u64 [%0], %1;"
                     :: "l"(&g_key[tt * 128 + tid]), "l"(keys[tid]) : "memory");
    }
}

// --------------------- EMA scatter (counts, dw) ------------------------------
__global__ void ema_scatter_kernel(const float* __restrict__ z_e) {
    int id = blockIdx.x * blockDim.x + threadIdx.x;   // over Ntok * Cc, n fastest
    if (id >= Ntok * Cc) return;
    int n = id & (Ntok - 1);
    int c = id >> 14;
    int b = n >> 10, hw = n & (HW - 1);
    float v = z_e[(size_t)b * Cc * HW + c * HW + hw];
    int e = (int)(g_key[n] & 0xFFFFFFFFull);
    atomicAdd(&g_dw[e * Cc + c], v);
    if (c == 0) atomicAdd(&g_counts[e], 1.0f);
}

// --------------------- gather outputs (z_q_st, z_q, indices) -----------------
__global__ void outputs_kernel(const float* __restrict__ z_e,
                               const float* __restrict__ emb,
                               float* __restrict__ out)
{
    int id = blockIdx.x * blockDim.x + threadIdx.x;   // over B*C*H*W / 4
    if (id >= Bb * Cc * HW / 4) return;
    int hwq = id & 255;
    int c   = (id >> 8) & 63;
    int b   = id >> 14;
    int nb  = b * HW + hwq * 4;

    float4 ze = reinterpret_cast<const float4*>(z_e)[id];
    int e0 = (int)(g_key[nb + 0] & 0xFFFFFFFFull);
    int e1 = (int)(g_key[nb + 1] & 0xFFFFFFFFull);
    int e2 = (int)(g_key[nb + 2] & 0xFFFFFFFFull);
    int e3 = (int)(g_key[nb + 3] & 0xFFFFFFFFull);
    float4 zq;
    zq.x = emb[e0 * Cc + c];
    zq.y = emb[e1 * Cc + c];
    zq.z = emb[e2 * Cc + c];
    zq.w = emb[e3 * Cc + c];
    float4 st;
    st.x = ze.x + (zq.x - ze.x);
    st.y = ze.y + (zq.y - ze.y);
    st.z = ze.z + (zq.z - ze.z);
    st.w = ze.w + (zq.w - ze.w);
    reinterpret_cast<float4*>(out + O_ZQST)[id] = st;
    reinterpret_cast<float4*>(out + O_ZQ)[id]   = zq;

    if (id < Ntok / 4) {
        int n = id * 4;
        float4 ix;
        ix.x = (float)(int)(g_key[n + 0] & 0xFFFFFFFFull);
        ix.y = (float)(int)(g_key[n + 1] & 0xFFFFFFFFull);
        ix.z = (float)(int)(g_key[n + 2] & 0xFFFFFFFFull);
        ix.w = (float)(int)(g_key[n + 3] & 0xFFFFFFFFull);
        reinterpret_cast<float4*>(out + O_IDX)[id] = ix;
    }
}

// --------------------- EMA blend + n reduction -------------------------------
__global__ void finalize1_kernel(const float* __restrict__ cs_in,
                                 const float* __restrict__ avg_in,
                                 float* __restrict__ out)
{
    int id = blockIdx.x * blockDim.x + threadIdx.x;   // over K*C/4
    if (id >= Kc * Cc / 4) return;
    float4 av = reinterpret_cast<const float4*>(avg_in)[id];
    float4 dw = reinterpret_cast<const float4*>(g_dw)[id];
    float4 r;
    r.x = DECAYF * av.x + ONE_MINUS_DECAYF * dw.x;
    r.y = DECAYF * av.y + ONE_MINUS_DECAYF * dw.y;
    r.z = DECAYF * av.z + ONE_MINUS_DECAYF * dw.z;
    r.w = DECAYF * av.w + ONE_MINUS_DECAYF * dw.w;
    reinterpret_cast<float4*>(out + O_AVG)[id] = r;

    if (id < Kc / 4) {
        float4 cv = reinterpret_cast<const float4*>(cs_in)[id];
        float4 ct = reinterpret_cast<const float4*>(g_counts)[id];
        float4 cs;
        cs.x = DECAYF * cv.x + ONE_MINUS_DECAYF * ct.x;
        cs.y = DECAYF * cv.y + ONE_MINUS_DECAYF * ct.y;
        cs.z = DECAYF * cv.z + ONE_MINUS_DECAYF * ct.z;
        cs.w = DECAYF * cv.w + ONE_MINUS_DECAYF * ct.w;
        reinterpret_cast<float4*>(out + O_CS)[id] = cs;
        float local = cs.x + cs.y + cs.z + cs.w;
#pragma unroll
        for (int off = 16; off >= 1; off >>= 1)
            local += __shfl_xor_sync(0xffffffffu, local, off);
        if ((threadIdx.x & 31) == 0) atomicAdd(g_n, local);
    }
}

// --------------------- normalized embedding ----------------------------------
__global__ void finalize2_kernel(float* __restrict__ out) {
    int id = blockIdx.x * blockDim.x + threadIdx.x;   // over K*C/4
    if (id >= Kc * Cc / 4) return;
    int k = id >> 4;
    float n = g_n[0];
    float csv = out[O_CS + k];
    float cs = (csv + EPSF) / (n + (float)Kc * EPSF) * n;
    float inv = 1.0f / cs;
    float4 av = reinterpret_cast<const float4*>(out + O_AVG)[id];
    float4 r;
    r.x = av.x * inv; r.y = av.y * inv; r.z = av.z * inv; r.w = av.w * inv;
    reinterpret_cast<float4*>(out + O_EMB)[id] = r;
}

// --------------------- launcher ---------------------------------------------
extern "C" void kernel_launch(void* const* d_in, const int* in_sizes, int n_in,
                              void* d_out, int out_size)
{
    const float* z_e = (const float*)d_in[0];
    const float* emb = (const float*)d_in[1];
    const float* cs  = (const float*)d_in[2];
    const float* avg = (const float*)d_in[3];
    float* out = (float*)d_out;

    cudaFuncSetAttribute(argmin_kernel,
                         cudaFuncAttributeMaxDynamicSharedMemorySize, ARG_SMEM);

    zero_dw_kernel<<<(Kc * Cc / 4 + 255) / 256, 256>>>();
    zero_misc_kernel<<<(Ntok + 255) / 256, 256>>>();
    enorm_kernel<<<(Kc + 255) / 256, 256>>>(emb);
    zsplit_kernel<<<Ntok / 64, 256>>>(z_e);
    esplit_kernel<<<(Kc * 32 + 255) / 256, 256>>>(emb);
    argmin_kernel<<<128 * 64, 256, ARG_SMEM>>>();
    ema_scatter_kernel<<<(Ntok * Cc + 255) / 256, 256>>>(z_e);
    outputs_kernel<<<(Bb * Cc * HW / 4 + 255) / 256, 256>>>(z_e, emb, out);
    finalize1_kernel<<<(Kc * Cc / 4 + 255) / 256, 256>>>(cs, avg, out);
    finalize2_kernel<<<(Kc * Cc / 4 + 255) / 256, 256>>>(out);
}

// round 9
// speedup vs baseline: 2.0140x; 1.3506x over previous
#include <cuda_runtime.h>
#include <cuda_bf16.h>
#include <math_constants.h>
#include <cstdint>

typedef unsigned long long u64;
typedef unsigned int       u32;
typedef unsigned short     u16;

// Problem constants
#define Bb 16
#define Cc 64
#define HW 1024
#define Ntok 16384
#define Kc 8192
#define DECAYF 0.99f
#define ONE_MINUS_DECAYF 0.01f
#define EPSF 1e-5f

// Output layout (float32, reference-return order)
#define O_ZQST 0
#define O_IDX  1048576
#define O_ZQ   1064960
#define O_EMB  2113536
#define O_CS   2637824
#define O_AVG  2646016

// --------------------- scratch (device globals) ------------------------------
__device__ u32   g_Bbf[Kc * 32];    // bf16 codebook, code-major rows of 64 bf16
__device__ float g_enorm[Kc];
__device__ u32   g_maxen;           // bits of max ||e||^2 (positive float)
__device__ int   g_idx[Ntok];
__device__ float g_counts[Kc];
__device__ float g_dw[Kc * Cc];
__device__ float g_n[1];

// --------------------- helpers ----------------------------------------------
__device__ __forceinline__ u32 fmono(float f) {
    u32 u = __float_as_uint(f);
    return u ^ ((u32)(((int)u) >> 31) | 0x80000000u);
}
__device__ __forceinline__ float inv_fmono(u32 m) {
    u32 u = (m & 0x80000000u) ? (m ^ 0x80000000u) : ~m;
    return __uint_as_float(u);
}
__device__ __forceinline__ u32 smem_u32(const void* p) {
    u32 a;
    asm("{ .reg .u64 t; cvta.to.shared.u64 t, %1; cvt.u32.u64 %0, t; }" : "=r"(a) : "l"(p));
    return a;
}
#define CP_ASYNC16(dst, src) \
    asm volatile("cp.async.cg.shared.global [%0], [%1], 16;" :: "r"(dst), "l"(src))
#define CP_COMMIT() asm volatile("cp.async.commit_group;" ::: "memory")
#define CP_WAIT(n)  asm volatile("cp.async.wait_group %0;" :: "n"(n) : "memory")

__device__ __forceinline__ void mma16816(float* d, const u32* a, const u32* b) {
    asm volatile("mma.sync.aligned.m16n8k16.row.col.f32.bf16.bf16.f32 "
        "{%0,%1,%2,%3}, {%4,%5,%6,%7}, {%8,%9}, {%0,%1,%2,%3};"
        : "+f"(d[0]), "+f"(d[1]), "+f"(d[2]), "+f"(d[3])
        : "r"(a[0]), "r"(a[1]), "r"(a[2]), "r"(a[3]), "r"(b[0]), "r"(b[1]));
}

// --------------------- zero / init kernels -----------------------------------
__global__ void zero_dw_kernel() {
    int id = blockIdx.x * blockDim.x + threadIdx.x;
    if (id < Kc * Cc / 4) reinterpret_cast<float4*>(g_dw)[id] = make_float4(0, 0, 0, 0);
}
__global__ void zero_misc_kernel() {
    int id = blockIdx.x * blockDim.x + threadIdx.x;
    if (id < Kc) g_counts[id] = 0.0f;
    if (id == 0) { g_n[0] = 0.0f; g_maxen = 0u; }
}

// --------------------- ||e||^2 + global max norm ------------------------------
__global__ void enorm_kernel(const float* __restrict__ emb) {
    int k = blockIdx.x * blockDim.x + threadIdx.x;
    if (k >= Kc) return;
    const float4* p = reinterpret_cast<const float4*>(emb + (size_t)k * Cc);
    float s = 0.0f;
#pragma unroll
    for (int i = 0; i < Cc / 4; i++) {
        float4 v = p[i];
        s += v.x * v.x + v.y * v.y + v.z * v.z + v.w * v.w;
    }
    g_enorm[k] = s;
    atomicMax(&g_maxen, __float_as_uint(s));   // positive floats: bit order == value order
}

// --------------------- bf16 codebook -----------------------------------------
__global__ void __launch_bounds__(256) ebf_kernel(const float* __restrict__ emb) {
    int id = blockIdx.x * blockDim.x + threadIdx.x;   // over Kc*32
    if (id >= Kc * 32) return;
    float2 e2 = reinterpret_cast<const float2*>(emb)[id];
    u16 h0 = __bfloat16_as_ushort(__float2bfloat16(e2.x));
    u16 h1 = __bfloat16_as_ushort(__float2bfloat16(e2.y));
    g_Bbf[id] = (u32)h0 | ((u32)h1 << 16);
}

// --------------------- argmin: coarse bf16 GEMM + candidates + fp32 refine ---
// 128 persistent CTAs x 256 threads; CTA owns 128 tokens, scans 64 code tiles
// of 128. 8 warps as 4(m) x 2(n), warp tile 32x64 via m16n8k16 bf16.
#define ROWB 144
#define B_STAGE 18432
#define CAP 64

#define SM_EN     0          // 32768: ||e||^2 fp32
#define SM_ZF     32768      // 34816: z fp32 [128][68]
#define SM_ABF    67584      // 18432: bf16(-2z) [128 rows x 128B, stride 144]
#define SM_B      86016      // 2 x 18432: B tiles
#define SM_MINKEY 122880     // 512: u32 fmono coarse min per token
#define SM_THR    123392     // 512: f32 threshold per token
#define SM_MARG   123904     // 512: f32 margin per token
#define SM_CNT    124416     // 512: u32 candidate count per token
#define SM_CAND   124928     // 16384: u16 [128][CAP]
#define ARG_SMEM  141312

__global__ void __launch_bounds__(256, 1) argmin_kernel(
    const float* __restrict__ z_e,
    const float* __restrict__ emb)
{
    extern __shared__ char smem[];
    const u32 sb = smem_u32(smem);
    const int tid = threadIdx.x;
    const int lane = tid & 31;
    const int wid = tid >> 5;
    const int warp_m = wid >> 1, warp_n = wid & 1;
    const int gID = lane >> 2, tg = lane & 3;
    const int n0 = blockIdx.x * 128;
    const int b = n0 >> 10, hw0 = n0 & (HW - 1);

    float* en_s = reinterpret_cast<float*>(smem + SM_EN);
    float* zf   = reinterpret_cast<float*>(smem + SM_ZF);
    u32*   mink = reinterpret_cast<u32*>(smem + SM_MINKEY);
    float* thr  = reinterpret_cast<float*>(smem + SM_THR);
    float* marg = reinterpret_cast<float*>(smem + SM_MARG);
    u32*   cnt  = reinterpret_cast<u32*>(smem + SM_CNT);
    u16*   cand = reinterpret_cast<u16*>(smem + SM_CAND);

    // ---- prologue: en, zf (transposed), init ----
    for (int j = tid; j < Kc / 4; j += 256)
        reinterpret_cast<float4*>(en_s)[j] = reinterpret_cast<const float4*>(g_enorm)[j];
    for (int i = tid; i < Cc * 128; i += 256) {
        int c = i >> 7, t = i & 127;
        zf[t * 68 + c] = z_e[(size_t)b * Cc * HW + c * HW + hw0 + t];
    }
    if (tid < 128) { mink[tid] = 0xFFFFFFFFu; cnt[tid] = 0u; }
    __syncthreads();

    // bf16(-2z) tile for MMA A operand
    for (int i = tid; i < 128 * 32; i += 256) {
        int t = i >> 5, cp = i & 31;
        float x0 = -2.0f * zf[t * 68 + 2 * cp];
        float x1 = -2.0f * zf[t * 68 + 2 * cp + 1];
        u16 h0 = __bfloat16_as_ushort(__float2bfloat16(x0));
        u16 h1 = __bfloat16_as_ushort(__float2bfloat16(x1));
        reinterpret_cast<u32*>(smem + SM_ABF)[t * 36 + cp] = (u32)h0 | ((u32)h1 << 16);
    }
    // per-token margin: 2E bound for 1-term bf16 coarse distances
    if (tid < 128) {
        float s = 0.0f;
        for (int i = 0; i < Cc; i++) { float v = zf[tid * 68 + i]; s += v * v; }
        float maxe = sqrtf(__uint_as_float(g_maxen));
        marg[tid] = 0.0158f * sqrtf(s) * maxe + 0.003f;
    }
    __syncthreads();

    // ---- B tile pipeline ----
    auto loadB = [&](int ct, int s) {
        const char* gB = reinterpret_cast<const char*>(g_Bbf) + (size_t)ct * 128 * 128;
        u32 dst0 = sb + SM_B + s * B_STAGE;
        for (int j = tid; j < 1024; j += 256) {
            int r = j >> 3, c = j & 7;
            CP_ASYNC16(dst0 + r * ROWB + c * 16, gB + r * 128 + c * 16);
        }
    };
    loadB(0, 0);
    CP_COMMIT();

    const char* aB = smem + SM_ABF + (warp_m * 32 + gID) * ROWB + tg * 4;

    for (int ct = 0; ct < 64; ct++) {
        if (ct + 1 < 64) { loadB(ct + 1, (ct + 1) & 1); CP_COMMIT(); CP_WAIT(1); }
        else             { CP_WAIT(0); }
        __syncthreads();

        float d[2][8][4];
#pragma unroll
        for (int mt = 0; mt < 2; mt++)
#pragma unroll
            for (int nt = 0; nt < 8; nt++)
#pragma unroll
                for (int i = 0; i < 4; i++) d[mt][nt][i] = 0.0f;

        const char* bB = smem + SM_B + (ct & 1) * B_STAGE
                       + (warp_n * 64 + gID) * ROWB + tg * 4;
#pragma unroll
        for (int ks = 0; ks < 4; ks++) {
            u32 a[2][4];
#pragma unroll
            for (int mt = 0; mt < 2; mt++) {
                const char* p = aB + mt * (16 * ROWB) + ks * 32;
                a[mt][0] = *reinterpret_cast<const u32*>(p);
                a[mt][1] = *reinterpret_cast<const u32*>(p + 8 * ROWB);
                a[mt][2] = *reinterpret_cast<const u32*>(p + 16);
                a[mt][3] = *reinterpret_cast<const u32*>(p + 8 * ROWB + 16);
            }
#pragma unroll
            for (int nt = 0; nt < 8; nt++) {
                u32 bfr[2];
                const char* p = bB + nt * (8 * ROWB) + ks * 32;
                bfr[0] = *reinterpret_cast<const u32*>(p);
                bfr[1] = *reinterpret_cast<const u32*>(p + 16);
                mma16816(d[0][nt], a[0], bfr);
                mma16816(d[1][nt], a[1], bfr);
            }
        }

        // tile row-min -> shared coarse min
        const float* ent = en_s + ct * 128 + warp_n * 64;
#pragma unroll
        for (int mt = 0; mt < 2; mt++)
#pragma unroll
            for (int h = 0; h < 2; h++) {
                int row = warp_m * 32 + mt * 16 + h * 8 + gID;
                float rm = CUDART_INF_F;
#pragma unroll
                for (int nt = 0; nt < 8; nt++)
#pragma unroll
                    for (int c = 0; c < 2; c++) {
                        float v = ent[nt * 8 + tg * 2 + c] + d[mt][nt][h * 2 + c];
                        rm = fminf(rm, v);
                    }
                atomicMin(&mink[row], fmono(rm));
            }
        __syncthreads();
        if (tid < 128) thr[tid] = inv_fmono(mink[tid]) + marg[tid];
        __syncthreads();

        // compare & append candidates (accumulators still live)
#pragma unroll
        for (int mt = 0; mt < 2; mt++)
#pragma unroll
            for (int h = 0; h < 2; h++) {
                int row = warp_m * 32 + mt * 16 + h * 8 + gID;
                float th = thr[row];
#pragma unroll
                for (int nt = 0; nt < 8; nt++)
#pragma unroll
                    for (int c = 0; c < 2; c++) {
                        int col = warp_n * 64 + nt * 8 + tg * 2 + c;
                        float v = en_s[ct * 128 + col] + d[mt][nt][h * 2 + c];
                        if (v <= th) {
                            u32 pos = atomicAdd(&cnt[row], 1u);
                            if (pos < CAP) cand[row * CAP + pos] = (u16)(ct * 128 + col);
                        }
                    }
            }
        __syncthreads();
    }

    // ---- refine: exact fp32 over candidates (or full scan on overflow) ----
    for (int tt = 0; tt < 16; tt++) {
        int t = wid * 16 + tt;
        u32 n = cnt[t];
        float bv = CUDART_INF_F;
        int bi = 0x7FFFFFFF;
        const float4* zf4 = reinterpret_cast<const float4*>(zf + t * 68);
        if (n <= CAP) {
            if (lane < (int)n) {
                int c = cand[t * CAP + lane];
                const float4* e4 = reinterpret_cast<const float4*>(emb + (size_t)c * Cc);
                float dot = 0.0f;
#pragma unroll
                for (int i = 0; i < 16; i++) {
                    float4 zv = zf4[i], ev = e4[i];
                    dot = fmaf(zv.x, ev.x, dot);
                    dot = fmaf(zv.y, ev.y, dot);
                    dot = fmaf(zv.z, ev.z, dot);
                    dot = fmaf(zv.w, ev.w, dot);
                }
                bv = fmaf(-2.0f, dot, en_s[c]);
                bi = c;
            }
        } else {
            for (int c = lane; c < Kc; c += 32) {
                const float4* e4 = reinterpret_cast<const float4*>(emb + (size_t)c * Cc);
                float dot = 0.0f;
#pragma unroll
                for (int i = 0; i < 16; i++) {
                    float4 zv = zf4[i], ev = e4[i];
                    dot = fmaf(zv.x, ev.x, dot);
                    dot = fmaf(zv.y, ev.y, dot);
                    dot = fmaf(zv.z, ev.z, dot);
                    dot = fmaf(zv.w, ev.w, dot);
                }
                float v = fmaf(-2.0f, dot, en_s[c]);
                if (v < bv || (v == bv && c < bi)) { bv = v; bi = c; }
            }
        }
#pragma unroll
        for (int off = 16; off >= 1; off >>= 1) {
            float ov = __shfl_xor_sync(0xffffffffu, bv, off);
            int   oi = __shfl_xor_sync(0xffffffffu, bi, off);
            if (ov < bv || (ov == bv && oi < bi)) { bv = ov; bi = oi; }
        }
        if (lane == 0) g_idx[n0 + t] = bi;
    }
}

// --------------------- EMA scatter (counts, dw) ------------------------------
__global__ void ema_scatter_kernel(const float* __restrict__ z_e) {
    int id = blockIdx.x * blockDim.x + threadIdx.x;   // over Ntok * Cc, n fastest
    if (id >= Ntok * Cc) return;
    int n = id & (Ntok - 1);
    int c = id >> 14;
    int b = n >> 10, hw = n & (HW - 1);
    float v = z_e[(size_t)b * Cc * HW + c * HW + hw];
    int e = g_idx[n];
    atomicAdd(&g_dw[e * Cc + c], v);
    if (c == 0) atomicAdd(&g_counts[e], 1.0f);
}

// --------------------- gather outputs (z_q_st, z_q, indices) -----------------
__global__ void outputs_kernel(const float* __restrict__ z_e,
                               const float* __restrict__ emb,
                               float* __restrict__ out)
{
    int id = blockIdx.x * blockDim.x + threadIdx.x;   // over B*C*H*W / 4
    if (id >= Bb * Cc * HW / 4) return;
    int hwq = id & 255;
    int c   = (id >> 8) & 63;
    int b   = id >> 14;
    int nb  = b * HW + hwq * 4;

    float4 ze = reinterpret_cast<const float4*>(z_e)[id];
    int e0 = g_idx[nb + 0], e1 = g_idx[nb + 1], e2 = g_idx[nb + 2], e3 = g_idx[nb + 3];
    float4 zq;
    zq.x = emb[e0 * Cc + c];
    zq.y = emb[e1 * Cc + c];
    zq.z = emb[e2 * Cc + c];
    zq.w = emb[e3 * Cc + c];
    float4 st;
    st.x = ze.x + (zq.x - ze.x);
    st.y = ze.y + (zq.y - ze.y);
    st.z = ze.z + (zq.z - ze.z);
    st.w = ze.w + (zq.w - ze.w);
    reinterpret_cast<float4*>(out + O_ZQST)[id] = st;
    reinterpret_cast<float4*>(out + O_ZQ)[id]   = zq;

    if (id < Ntok / 4) {
        int n = id * 4;
        float4 ix;
        ix.x = (float)g_idx[n + 0];
        ix.y = (float)g_idx[n + 1];
        ix.z = (float)g_idx[n + 2];
        ix.w = (float)g_idx[n + 3];
        reinterpret_cast<float4*>(out + O_IDX)[id] = ix;
    }
}

// --------------------- EMA blend + n reduction -------------------------------
__global__ void finalize1_kernel(const float* __restrict__ cs_in,
                                 const float* __restrict__ avg_in,
                                 float* __restrict__ out)
{
    int id = blockIdx.x * blockDim.x + threadIdx.x;   // over K*C/4
    if (id >= Kc * Cc / 4) return;
    float4 av = reinterpret_cast<const float4*>(avg_in)[id];
    float4 dw = reinterpret_cast<const float4*>(g_dw)[id];
    float4 r;
    r.x = DECAYF * av.x + ONE_MINUS_DECAYF * dw.x;
    r.y = DECAYF * av.y + ONE_MINUS_DECAYF * dw.y;
    r.z = DECAYF * av.z + ONE_MINUS_DECAYF * dw.z;
    r.w = DECAYF * av.w + ONE_MINUS_DECAYF * dw.w;
    reinterpret_cast<float4*>(out + O_AVG)[id] = r;

    if (id < Kc / 4) {
        float4 cv = reinterpret_cast<const float4*>(cs_in)[id];
        float4 ct = reinterpret_cast<const float4*>(g_counts)[id];
        float4 cs;
        cs.x = DECAYF * cv.x + ONE_MINUS_DECAYF * ct.x;
        cs.y = DECAYF * cv.y + ONE_MINUS_DECAYF * ct.y;
        cs.z = DECAYF * cv.z + ONE_MINUS_DECAYF * ct.z;
        cs.w = DECAYF * cv.w + ONE_MINUS_DECAYF * ct.w;
        reinterpret_cast<float4*>(out + O_CS)[id] = cs;
        float local = cs.x + cs.y + cs.z + cs.w;
#pragma unroll
        for (int off = 16; off >= 1; off >>= 1)
            local += __shfl_xor_sync(0xffffffffu, local, off);
        if ((threadIdx.x & 31) == 0) atomicAdd(g_n, local);
    }
}

// --------------------- normalized embedding ----------------------------------
__global__ void finalize2_kernel(float* __restrict__ out) {
    int id = blockIdx.x * blockDim.x + threadIdx.x;   // over K*C/4
    if (id >= Kc * Cc / 4) return;
    int k = id >> 4;
    float n = g_n[0];
    float csv = out[O_CS + k];
    float cs = (csv + EPSF) / (n + (float)Kc * EPSF) * n;
    float inv = 1.0f / cs;
    float4 av = reinterpret_cast<const float4*>(out + O_AVG)[id];
    float4 r;
    r.x = av.x * inv; r.y = av.y * inv; r.z = av.z * inv; r.w = av.w * inv;
    reinterpret_cast<float4*>(out + O_EMB)[id] = r;
}

// --------------------- launcher ---------------------------------------------
extern "C" void kernel_launch(void* const* d_in, const int* in_sizes, int n_in,
                              void* d_out, int out_size)
{
    const float* z_e = (const float*)d_in[0];
    const float* emb = (const float*)d_in[1];
    const float* cs  = (const float*)d_in[2];
    const float* avg = (const float*)d_in[3];
    float* out = (float*)d_out;

    cudaFuncSetAttribute(argmin_kernel,
                         cudaFuncAttributeMaxDynamicSharedMemorySize, ARG_SMEM);

    zero_dw_kernel<<<(Kc * Cc / 4 + 255) / 256, 256>>>();
    zero_misc_kernel<<<(Kc + 255) / 256, 256>>>();
    enorm_kernel<<<(Kc + 255) / 256, 256>>>(emb);
    ebf_kernel<<<(Kc * 32 + 255) / 256, 256>>>(emb);
    argmin_kernel<<<Ntok / 128, 256, ARG_SMEM>>>(z_e, emb);
    ema_scatter_kernel<<<(Ntok * Cc + 255) / 256, 256>>>(z_e);
    outputs_kernel<<<(Bb * Cc * HW / 4 + 255) / 256, 256>>>(z_e, emb, out);
    finalize1_kernel<<<(Kc * Cc / 4 + 255) / 256, 256>>>(cs, avg, out);
    finalize2_kernel<<<(Kc * Cc / 4 + 255) / 256, 256>>>(out);
}